// round 8
// baseline (speedup 1.0000x reference)
#include <cuda_runtime.h>

#define BB 2
#define CC 128
#define TT 5
#define HH 48
#define WW 48
#define HWP 2304      // H*W
#define NH 64         // heads
#define TC 4          // context frames
#define NK 196        // Tc*7*7
#define FRAME (TC * HWP)
#define TQ 4          // query pixels per attn block
#define TW 10         // tile width  (7 + TQ - 1)
#define NTILE 280     // TC * 7 * TW
#define HCH 32        // head chunk

// Scratch (allocation-free rule: __device__ globals)
__device__ float g_q   [BB * HWP * NH];      // [b][pix][h]
__device__ float g_phiT[BB * NH * FRAME];    // [b][h][t][pix]
__device__ float g_gvT [BB * NH * FRAME];    // [b][h][t][pix]
__device__ float g_z   [BB * HWP * NH];      // [b][p2][h2]  (scrambled Y)

typedef unsigned long long u64t;
__device__ __forceinline__ u64t pk2(float lo, float hi) {
    u64t r; asm("mov.b64 %0,{%1,%2};" : "=l"(r) : "f"(lo), "f"(hi)); return r;
}
__device__ __forceinline__ void upk2(u64t v, float& lo, float& hi) {
    asm("mov.b64 {%0,%1},%2;" : "=f"(lo), "=f"(hi) : "l"(v));
}
#define FMA2(d, a, b, c) asm("fma.rn.f32x2 %0,%1,%2,%3;" : "=l"(d) : "l"(a), "l"(b), "l"(c))

#define TP 32  // pixels per projection tile
#define NPB (HWP / TP)          // 72

// ---------------------------------------------------------------------------
// Merged projections (f32x2 packed math).
// blocks [0, BB*TC*NPB): ctx (phi+g). Rest: query theta.
// ---------------------------------------------------------------------------
__global__ __launch_bounds__(128) void proj_kernel(
        const float* __restrict__ x,
        const float* __restrict__ w_theta,
        const float* __restrict__ w_phi,
        const float* __restrict__ w_g) {
    __shared__ __align__(16) float xs[CC][TP];
    int blk = blockIdx.x;

    if (blk < BB * TC * NPB) {
        // ----- context frames: phi -> g_phiT, g -> g_gvT -----
        int pb = blk % NPB;
        int t  = (blk / NPB) % TC;
        int b  = blk / (NPB * TC);
        int pix0 = pb * TP;

        const float* xb = x + ((long)(b * CC) * TT + (t + 1)) * HWP + pix0;
        for (int i = threadIdx.x; i < CC * TP; i += 128) {
            int c = i / TP, pp = i % TP;
            xs[c][pp] = xb[(long)c * TT * HWP + pp];
        }
        __syncthreads();

        int r = threadIdx.x;
        const float* wr = (r < NH) ? (w_phi + r * CC) : (w_g + (r - NH) * CC);

        u64t acc2[16];
#pragma unroll
        for (int v = 0; v < 16; v++) acc2[v] = 0ull;

        for (int c = 0; c < CC; c++) {
            float w = wr[c];
            u64t w2 = pk2(w, w);
            const ulonglong2* xr = (const ulonglong2*)&xs[c][0];   // 8 x 16B
#pragma unroll
            for (int v = 0; v < 8; v++) {
                ulonglong2 p = xr[v];
                FMA2(acc2[2*v],     w2, p.x, acc2[2*v]);
                FMA2(acc2[2*v + 1], w2, p.y, acc2[2*v + 1]);
            }
        }

        float af[TP];
#pragma unroll
        for (int v = 0; v < 16; v++) upk2(acc2[v], af[2*v], af[2*v+1]);

        float* ob = ((r < NH) ? g_phiT : g_gvT)
                  + ((long)(b * NH + (r & (NH - 1))) * TC + t) * HWP + pix0;
#pragma unroll
        for (int pp = 0; pp < TP; pp += 4)
            *(float4*)(ob + pp) = make_float4(af[pp], af[pp+1], af[pp+2], af[pp+3]);
    } else {
        // ----- query frame: theta -> g_q -----
        int blk2 = blk - BB * TC * NPB;
        int pb = blk2 % NPB;
        int b  = blk2 / NPB;
        int pix0 = pb * TP;

        const float* xb = x + ((long)(b * CC) * TT) * HWP + pix0;
        for (int i = threadIdx.x; i < CC * TP; i += 128) {
            int c = i / TP, pp = i % TP;
            xs[c][pp] = xb[(long)c * TT * HWP + pp];
        }
        __syncthreads();

        int r  = threadIdx.x & 63;
        int hf = threadIdx.x >> 6;      // pixel half (16 px each)
        const float* wr = w_theta + r * CC;

        u64t acc2[8];
#pragma unroll
        for (int v = 0; v < 8; v++) acc2[v] = 0ull;

        for (int c = 0; c < CC; c++) {
            float w = wr[c];
            u64t w2 = pk2(w, w);
            const ulonglong2* xr = (const ulonglong2*)&xs[c][hf * 16];
#pragma unroll
            for (int v = 0; v < 4; v++) {
                ulonglong2 p = xr[v];
                FMA2(acc2[2*v],     w2, p.x, acc2[2*v]);
                FMA2(acc2[2*v + 1], w2, p.y, acc2[2*v + 1]);
            }
        }

        float af[16];
#pragma unroll
        for (int v = 0; v < 8; v++) upk2(acc2[v], af[2*v], af[2*v+1]);

        long base = (long)b * HWP + pix0 + hf * 16;
#pragma unroll
        for (int pp = 0; pp < 16; pp++) g_q[(base + pp) * NH + r] = af[pp];
    }
}

// ---------------------------------------------------------------------------
// Attention, TQ=4 query pixels per block. Window union (4 frames x 7 rows x
// 10 cols) staged in smem per 32-head chunk; buffer reused phi then g.
// 256 threads. Branchless scrambled AV. Writes scrambled Z.
// ---------------------------------------------------------------------------
__global__ __launch_bounds__(256) void attn_kernel() {
    __shared__ float tile[HCH * NTILE];   // 35840 B
    __shared__ float att_s[TQ][NK];
    __shared__ float qs[TQ][NH];
    __shared__ int   kpos[NK];            // key -> tile position (query 0)
    __shared__ int   toff[NTILE];         // tile idx -> frame-relative gmem offset
    __shared__ float redm[8], reds[8];

    int bq   = blockIdx.x;
    int b    = bq / (HWP / TQ);
    int pix0 = (bq % (HWP / TQ)) * TQ;
    int y0   = pix0 / WW;
    int x0   = pix0 % WW;                 // multiple of 4; row-contained
    int tid  = threadIdx.x;

    {   // q-vectors: coalesced
        int q = tid >> 6, h = tid & 63;
        qs[q][h] = g_q[((long)b * HWP + pix0 + q) * NH + h];
    }
    if (tid < NK) {
        int tf = tid / 49, o = tid % 49, i = o / 7, j = o % 7;
        kpos[tid] = (tf * 7 + i) * TW + j;
    }
    for (int e = tid; e < NTILE; e += 256) {
        int tf = e / 70, p = e % 70, i = p / TW, j = p % TW;
        int gy = min(max(y0 - 3 + i, 0), HH - 1);
        int gx = min(max(x0 - 3 + j, 0), WW - 1);
        toff[e] = tf * HWP + gy * WW + gx;
    }
    __syncthreads();

    const float* phib = g_phiT + (long)b * NH * FRAME;
    const float* gvb  = g_gvT  + (long)b * NH * FRAME;

    // ---- QK over two head chunks ----
    int qfix = tid & 3;                   // task stride 256 keeps q fixed
    for (int c = 0; c < 2; c++) {
        int h0 = c * HCH;
#pragma unroll 4
        for (int hl = 0; hl < HCH; hl++) {
            const float* src = phib + (long)(h0 + hl) * FRAME;
            float* dst = tile + hl * NTILE;
            for (int j = tid; j < NTILE; j += 256) dst[j] = src[toff[j]];
        }
        __syncthreads();

        float qreg[HCH];
#pragma unroll
        for (int hl = 0; hl < HCH; hl++) qreg[hl] = qs[qfix][h0 + hl];

        for (int task = tid; task < TQ * NK; task += 256) {
            int k   = task >> 2;
            int pos = kpos[k] + qfix;
            float d = 0.f;
#pragma unroll
            for (int hl = 0; hl < HCH; hl++)
                d += qreg[hl] * tile[hl * NTILE + pos];
            if (c == 0) att_s[qfix][k] = d;
            else        att_s[qfix][k] = (att_s[qfix][k] + d) * 8.0f;  // *sqrt(64)
        }
        __syncthreads();
    }

    // ---- softmax: 64 threads (2 warps) per query ----
    int q    = tid >> 6;
    int l    = tid & 63;
    int warp = tid >> 5;
    float m = -1e30f;
    for (int k = l; k < NK; k += 64) m = fmaxf(m, att_s[q][k]);
#pragma unroll
    for (int s = 16; s > 0; s >>= 1) m = fmaxf(m, __shfl_xor_sync(0xffffffffu, m, s));
    if ((tid & 31) == 0) redm[warp] = m;
    __syncthreads();
    m = fmaxf(redm[q * 2], redm[q * 2 + 1]);

    float ss = 0.f;
    for (int k = l; k < NK; k += 64) {
        float e = __expf(att_s[q][k] - m);
        att_s[q][k] = e;
        ss += e;
    }
#pragma unroll
    for (int s = 16; s > 0; s >>= 1) ss += __shfl_xor_sync(0xffffffffu, ss, s);
    if ((tid & 31) == 0) reds[warp] = ss;
    __syncthreads();
    float inv = 1.f / (reds[q * 2] + reds[q * 2 + 1]);
    for (int k = l; k < NK; k += 64) att_s[q][k] *= inv;
    __syncthreads();

    // ---- AV (scrambled, branchless): G[k,h']=g(head=(64k+h')/196, key=(64k+h')%196)
    float acc = 0.f;
    {
        unsigned int h1 = (unsigned int)l;
        int kmid = (int)((6335u - h1) >> 6);         // hh crosses 32 at flat=6272
        for (int c = 0; c < 2; c++) {
#pragma unroll 4
            for (int hl = 0; hl < HCH; hl++) {
                const float* src = gvb + (long)(c * HCH + hl) * FRAME;
                float* dst = tile + hl * NTILE;
                for (int j = tid; j < NTILE; j += 256) dst[j] = src[toff[j]];
            }
            __syncthreads();

            int klo = c ? kmid : 0;
            int khi = c ? NK   : kmid;
            int sub = c << 5;
#pragma unroll 4
            for (int k = klo; k < khi; k++) {
                unsigned int flat = (unsigned int)k * 64u + h1;
                unsigned int hh = flat / 196u;        // const-div -> mul/shift
                unsigned int kk = flat - hh * 196u;
                acc += att_s[q][k] * tile[((int)hh - sub) * NTILE + kpos[kk] + q];
            }
            __syncthreads();
        }
    }

    // scrambled Y store: Y[b,p,h'] -> Z[b, (p%36)*64+h', p/36]
    {
        int p  = pix0 + q;
        int p2 = (p % 36) * 64 + l;
        int h2 = p / 36;
        g_z[((long)b * HWP + p2) * NH + h2] = acc;
    }
}

// ---------------------------------------------------------------------------
// Out projection + residual (f32x2):
//   out[b,c,p2] = x[b,c,0,p2] + sum_h2 w_out[c,h2] * Z[b,p2,h2]
// block = 128 (c = tid), 32 pixels per block.
// ---------------------------------------------------------------------------
#define OPX 32
#define ZPITCH 36   // 16B-aligned row pitch, conflict-benign
__global__ __launch_bounds__(128) void outproj_kernel(
        const float* __restrict__ x,
        const float* __restrict__ w_out,
        float* __restrict__ out) {
    int blk = blockIdx.x;
    int b   = blk / (HWP / OPX);
    int p20 = (blk % (HWP / OPX)) * OPX;
    int tid = threadIdx.x;

    __shared__ __align__(16) float zs[NH][ZPITCH];   // [h2][px]
    for (int i = tid; i < OPX * NH; i += 128) {
        int h2 = i & (NH - 1);                       // coalesced g_z read
        int px = i >> 6;
        zs[h2][px] = g_z[((long)b * HWP + p20 + px) * NH + h2];
    }
    __syncthreads();

    int c = tid;
    const float* wr = w_out + c * NH;

    u64t acc2[16];
#pragma unroll
    for (int v = 0; v < 16; v++) acc2[v] = 0ull;

    for (int h2 = 0; h2 < NH; h2++) {
        float w = wr[h2];
        u64t w2 = pk2(w, w);
        const ulonglong2* zr = (const ulonglong2*)&zs[h2][0];
#pragma unroll
        for (int v = 0; v < 8; v++) {
            ulonglong2 p = zr[v];
            FMA2(acc2[2*v],     w2, p.x, acc2[2*v]);
            FMA2(acc2[2*v + 1], w2, p.y, acc2[2*v + 1]);
        }
    }

    float af[OPX];
#pragma unroll
    for (int v = 0; v < 16; v++) upk2(acc2[v], af[2*v], af[2*v+1]);

    const float* xr   = x   + (((long)(b * CC + c)) * TT + 0) * HWP + p20;
    float*       orow = out + ((long)(b * CC + c)) * HWP + p20;
#pragma unroll
    for (int j = 0; j < OPX; j += 4) {
        float4 xv = *(const float4*)(xr + j);
        *(float4*)(orow + j) = make_float4(xv.x + af[j],     xv.y + af[j + 1],
                                           xv.z + af[j + 2], xv.w + af[j + 3]);
    }
}

extern "C" void kernel_launch(void* const* d_in, const int* in_sizes, int n_in,
                              void* d_out, int out_size) {
    const float* x       = (const float*)d_in[0];
    const float* w_theta = (const float*)d_in[1];
    const float* w_phi   = (const float*)d_in[2];
    const float* w_g     = (const float*)d_in[3];
    const float* w_out   = (const float*)d_in[4];
    float* out = (float*)d_out;

    proj_kernel<<<BB * TC * NPB + BB * NPB, 128>>>(x, w_theta, w_phi, w_g);
    attn_kernel<<<BB * (HWP / TQ), 256>>>();
    outproj_kernel<<<BB * (HWP / OPX), 128>>>(x, w_out, out);
}

// round 11
// speedup vs baseline: 1.7459x; 1.7459x over previous
#include <cuda_runtime.h>

#define BB 2
#define CC 128
#define TT 5
#define HH 48
#define WW 48
#define HWP 2304      // H*W
#define NH 64         // heads
#define TC 4          // context frames
#define PAD 3
#define NK 196        // Tc*7*7
#define FRAME (TC * HWP)

// Scratch (allocation-free rule: __device__ globals)
__device__ float g_q   [BB * HWP * NH];      // [b][pix][h]
__device__ float g_phiT[BB * NH * FRAME];    // [b][h][t][pix]
__device__ float g_gvT [BB * NH * FRAME];    // [b][h][t][pix]
__device__ float g_z   [BB * HWP * NH];      // [b][p2][h2]  (scrambled Y)

typedef unsigned long long u64t;
__device__ __forceinline__ u64t pk2(float lo, float hi) {
    u64t r; asm("mov.b64 %0,{%1,%2};" : "=l"(r) : "f"(lo), "f"(hi)); return r;
}
__device__ __forceinline__ void upk2(u64t v, float& lo, float& hi) {
    asm("mov.b64 {%0,%1},%2;" : "=f"(lo), "=f"(hi) : "l"(v));
}
#define FMA2(d, a, b, c) asm("fma.rn.f32x2 %0,%1,%2,%3;" : "=l"(d) : "l"(a), "l"(b), "l"(c))

// ---------------------------------------------------------------------------
// Merged projections, weights staged TRANSPOSED in dynamic smem.
//   wst[c][r] (pitch 129 -> conflict-free transpose write AND lane-r read)
//   xs [c][px] (64-px tile, broadcast LDS.128 reads)
// blocks [0, 288): ctx (phi rows 0-63, g rows 64-127). blocks [288, 360): theta.
// ---------------------------------------------------------------------------
#define TPX 64
#define NPB (HWP / TPX)          // 36
#define WPITCH 129
#define SMEM_PROJ ((CC * TPX + CC * WPITCH) * 4)   // 98816 B

__global__ __launch_bounds__(128) void proj_kernel(
        const float* __restrict__ x,
        const float* __restrict__ w_theta,
        const float* __restrict__ w_phi,
        const float* __restrict__ w_g) {
    extern __shared__ float sm[];
    float* xs  = sm;                 // [CC][TPX]
    float* wst = sm + CC * TPX;      // [CC][WPITCH]

    int blk = blockIdx.x;
    int tid = threadIdx.x;

    if (blk < BB * TC * NPB) {
        // ----- context frames -----
        int pb = blk % NPB;
        int t  = (blk / NPB) % TC;
        int b  = blk / (NPB * TC);
        int pix0 = pb * TPX;

        // weights, transposed store: lanes c-consecutive -> stride 129 -> no conflicts
        for (int i = tid; i < NH * CC; i += 128) {
            int r = i >> 7, c = i & 127;
            wst[c * WPITCH + r]      = w_phi[i];
            wst[c * WPITCH + r + NH] = w_g[i];
        }
        // x tile: 2 rows of 256B per instruction, coalesced
        const float* xb = x + ((long)(b * CC) * TT + (t + 1)) * HWP + pix0;
        for (int i = tid; i < CC * TPX; i += 128) {
            int c = i >> 6, px = i & 63;
            xs[c * TPX + px] = xb[(long)c * TT * HWP + px];
        }
        __syncthreads();

        int r = tid;                       // output row 0..127
        u64t acc2[32];
#pragma unroll
        for (int v = 0; v < 32; v++) acc2[v] = 0ull;

        for (int c = 0; c < CC; c++) {
            float w = wst[c * WPITCH + r];          // conflict-free LDS
            u64t w2 = pk2(w, w);
            const ulonglong2* xr = (const ulonglong2*)(xs + c * TPX);
#pragma unroll
            for (int v = 0; v < 16; v++) {          // broadcast LDS.128
                ulonglong2 p = xr[v];
                FMA2(acc2[2*v],     w2, p.x, acc2[2*v]);
                FMA2(acc2[2*v + 1], w2, p.y, acc2[2*v + 1]);
            }
        }

        float af[TPX];
#pragma unroll
        for (int v = 0; v < 32; v++) upk2(acc2[v], af[2*v], af[2*v+1]);

        float* ob = ((r < NH) ? g_phiT : g_gvT)
                  + ((long)(b * NH + (r & (NH - 1))) * TC + t) * HWP + pix0;
#pragma unroll
        for (int pp = 0; pp < TPX; pp += 4)
            *(float4*)(ob + pp) = make_float4(af[pp], af[pp+1], af[pp+2], af[pp+3]);
    } else {
        // ----- query frame: theta -> g_q -----
        int blk2 = blk - BB * TC * NPB;
        int pb = blk2 % NPB;
        int b  = blk2 / NPB;
        int pix0 = pb * TPX;

        for (int i = tid; i < NH * CC; i += 128) {
            int r = i >> 7, c = i & 127;
            wst[c * WPITCH + r] = w_theta[i];
        }
        const float* xb = x + ((long)(b * CC) * TT) * HWP + pix0;
        for (int i = tid; i < CC * TPX; i += 128) {
            int c = i >> 6, px = i & 63;
            xs[c * TPX + px] = xb[(long)c * TT * HWP + px];
        }
        __syncthreads();

        int r  = tid & 63;
        int hf = tid >> 6;                 // 32-px half
        u64t acc2[16];
#pragma unroll
        for (int v = 0; v < 16; v++) acc2[v] = 0ull;

        for (int c = 0; c < CC; c++) {
            float w = wst[c * WPITCH + r];
            u64t w2 = pk2(w, w);
            const ulonglong2* xr = (const ulonglong2*)(xs + c * TPX + hf * 32);
#pragma unroll
            for (int v = 0; v < 8; v++) {
                ulonglong2 p = xr[v];
                FMA2(acc2[2*v],     w2, p.x, acc2[2*v]);
                FMA2(acc2[2*v + 1], w2, p.y, acc2[2*v + 1]);
            }
        }

        float af[32];
#pragma unroll
        for (int v = 0; v < 16; v++) upk2(acc2[v], af[2*v], af[2*v+1]);

        long base = (long)b * HWP + pix0 + hf * 32;
#pragma unroll
        for (int pp = 0; pp < 32; pp++) g_q[(base + pp) * NH + r] = af[pp];
    }
}

// ---------------------------------------------------------------------------
// Attention per query pixel (round-6 structure, measured fast):
// thread-per-key QK, softmax, branchless scrambled AV. block = 256.
//   AV scramble: G[k,h'] = g(head=(64k+h')/196, key=(64k+h')%196)
// Writes Y in the scrambled layout: Z[b][(p%36)*64+h'][p/36].
// ---------------------------------------------------------------------------
__global__ __launch_bounds__(256) void attn_kernel() {
    int bp  = blockIdx.x;               // 0 .. B*HWP-1
    int b   = bp / HWP;
    int pix = bp % HWP;
    int y0  = pix / WW;
    int x0  = pix % WW;
    int tid  = threadIdx.x;
    int warp = tid >> 5;
    int lane = tid & 31;

    __shared__ float qs[NH];
    __shared__ float att[NK];
    __shared__ int   ntp[NK];          // tf*HWP + neighbor pixel
    __shared__ float ypart[4][NH];
    __shared__ float red[16];

    if (tid < NH) qs[tid] = g_q[((long)b * HWP + pix) * NH + tid];

    if (tid < NK) {
        int k   = tid;
        int tf  = k / 49;
        int off = k % 49;
        int dy  = off / 7 - PAD;
        int dx  = off % 7 - PAD;
        int ny  = min(max(y0 + dy, 0), HH - 1);
        int nx  = min(max(x0 + dx, 0), WW - 1);
        ntp[k] = tf * HWP + ny * WW + nx;
    }
    __syncthreads();

    // ---- QK: one thread per key; 64 independent L2 loads, no shuffles ----
    if (tid < NK) {
        const float* pb0 = g_phiT + (long)b * NH * FRAME + ntp[tid];
        float d = 0.f;
#pragma unroll 8
        for (int h = 0; h < NH; h++)
            d += qs[h] * pb0[h * FRAME];
        att[tid] = d * 8.0f;            // * sqrt(64)
    }
    __syncthreads();

    // ---- softmax over 196 (8 warps; inactive lanes feed identities) ----
    float v = (tid < NK) ? att[tid] : -1e30f;
    float m = v;
#pragma unroll
    for (int s = 16; s > 0; s >>= 1) m = fmaxf(m, __shfl_xor_sync(0xffffffffu, m, s));
    if (lane == 0) red[warp] = m;
    __syncthreads();
    if (tid == 0) {
        float mm = red[0];
#pragma unroll
        for (int w = 1; w < 8; w++) mm = fmaxf(mm, red[w]);
        red[8] = mm;
    }
    __syncthreads();
    m = red[8];

    float e = (tid < NK) ? __expf(v - m) : 0.f;
    float ssum = e;
#pragma unroll
    for (int s = 16; s > 0; s >>= 1) ssum += __shfl_xor_sync(0xffffffffu, ssum, s);
    if (lane == 0) red[warp] = ssum;
    __syncthreads();
    if (tid == 0) {
        float t2 = red[0];
#pragma unroll
        for (int w = 1; w < 8; w++) t2 += red[w];
        red[9] = 1.f / t2;
    }
    __syncthreads();
    if (tid < NK) att[tid] = e * red[9];
    __syncthreads();

    // ---- AV (scrambled), branchless const-div, 4-way k-split ----
    {
        int q = tid >> 6;                 // 0..3
        int h = tid & (NH - 1);
        int kbeg = q * 49;
        const float* gbase = g_gvT + (long)b * NH * FRAME;

        float acc = 0.f;
#pragma unroll 7
        for (int k = kbeg; k < kbeg + 49; k++) {
            int flat = k * NH + h;
            int hh = flat / NK;           // constant divisor -> mul/shift
            int kk = flat - hh * NK;
            acc += att[k] * gbase[hh * FRAME + ntp[kk]];
        }
        ypart[q][h] = acc;
    }
    __syncthreads();
    if (tid < NH) {
        float yv = ypart[0][tid] + ypart[1][tid] + ypart[2][tid] + ypart[3][tid];
        // Y[b,p,h'] -> Z[b, (p%36)*64+h', p/36]
        int p2 = (pix % 36) * 64 + tid;
        int h2 = pix / 36;
        g_z[((long)b * HWP + p2) * NH + h2] = yv;
    }
}

// ---------------------------------------------------------------------------
// Out projection + residual (f32x2):
//   out[b,c,p2] = x[b,c,0,p2] + sum_h2 w_out[c,h2] * Z[b,p2,h2]
// block = 128 (c = tid), 32 pixels per block; coalesced Z loads.
// ---------------------------------------------------------------------------
#define OPX 32
#define ZPITCH 36   // 16B-aligned row pitch
__global__ __launch_bounds__(128) void outproj_kernel(
        const float* __restrict__ x,
        const float* __restrict__ w_out,
        float* __restrict__ out) {
    int blk = blockIdx.x;
    int b   = blk / (HWP / OPX);
    int p20 = (blk % (HWP / OPX)) * OPX;
    int tid = threadIdx.x;

    __shared__ __align__(16) float zs[NH][ZPITCH];   // [h2][px]
    for (int i = tid; i < OPX * NH; i += 128) {
        int h2 = i & (NH - 1);                       // coalesced g_z read
        int px = i >> 6;
        zs[h2][px] = g_z[((long)b * HWP + p20 + px) * NH + h2];
    }
    __syncthreads();

    int c = tid;
    const float* wr = w_out + c * NH;

    u64t acc2[16];
#pragma unroll
    for (int v = 0; v < 16; v++) acc2[v] = 0ull;

    for (int h2 = 0; h2 < NH; h2++) {
        float w = wr[h2];
        u64t w2 = pk2(w, w);
        const ulonglong2* zr = (const ulonglong2*)&zs[h2][0];
#pragma unroll
        for (int v = 0; v < 8; v++) {
            ulonglong2 p = zr[v];
            FMA2(acc2[2*v],     w2, p.x, acc2[2*v]);
            FMA2(acc2[2*v + 1], w2, p.y, acc2[2*v + 1]);
        }
    }

    float af[OPX];
#pragma unroll
    for (int v = 0; v < 16; v++) upk2(acc2[v], af[2*v], af[2*v+1]);

    const float* xr   = x   + (((long)(b * CC + c)) * TT + 0) * HWP + p20;
    float*       orow = out + ((long)(b * CC + c)) * HWP + p20;
#pragma unroll
    for (int j = 0; j < OPX; j += 4) {
        float4 xv = *(const float4*)(xr + j);
        *(float4*)(orow + j) = make_float4(xv.x + af[j],     xv.y + af[j + 1],
                                           xv.z + af[j + 2], xv.w + af[j + 3]);
    }
}

extern "C" void kernel_launch(void* const* d_in, const int* in_sizes, int n_in,
                              void* d_out, int out_size) {
    const float* x       = (const float*)d_in[0];
    const float* w_theta = (const float*)d_in[1];
    const float* w_phi   = (const float*)d_in[2];
    const float* w_g     = (const float*)d_in[3];
    const float* w_out   = (const float*)d_in[4];
    float* out = (float*)d_out;

    cudaFuncSetAttribute(proj_kernel,
                         cudaFuncAttributeMaxDynamicSharedMemorySize, SMEM_PROJ);

    proj_kernel<<<BB * TC * NPB + BB * NPB, 128, SMEM_PROJ>>>(x, w_theta, w_phi, w_g);
    attn_kernel<<<BB * HWP, 256>>>();
    outproj_kernel<<<BB * (HWP / OPX), 128>>>(x, w_out, out);
}

// round 13
// speedup vs baseline: 1.9227x; 1.1013x over previous
#include <cuda_runtime.h>

#define BB 2
#define CC 128
#define TT 5
#define HH 48
#define WW 48
#define HWP 2304      // H*W
#define NH 64         // heads
#define TC 4          // context frames
#define PAD 3
#define NK 196        // Tc*7*7
#define FRAME (TC * HWP)

// Scratch (allocation-free rule: __device__ globals)
__device__ float g_q   [BB * HWP * NH];      // [b][pix][h]
__device__ float g_phiT[BB * NH * FRAME];    // [b][h][t][pix]
__device__ float g_gvT [BB * NH * FRAME];    // [b][h][t][pix]
__device__ float g_z   [BB * HWP * NH];      // [b][p2][h2]  (scrambled Y)
__device__ float g_wcT [CC * CC];            // [c][r]: r<64 -> phi row, r>=64 -> g row
__device__ float g_wqT [CC * NH];            // [c][r]: theta rows

typedef unsigned long long u64t;
__device__ __forceinline__ u64t pk2(float lo, float hi) {
    u64t r; asm("mov.b64 %0,{%1,%2};" : "=l"(r) : "f"(lo), "f"(hi)); return r;
}
__device__ __forceinline__ void upk2(u64t v, float& lo, float& hi) {
    asm("mov.b64 {%0,%1},%2;" : "=f"(lo), "=f"(hi) : "l"(v));
}
#define FMA2(d, a, b, c) asm("fma.rn.f32x2 %0,%1,%2,%3;" : "=l"(d) : "l"(a), "l"(b), "l"(c))

// ---------------------------------------------------------------------------
// One-time weight transpose: w[r][c] -> wT[c][r]. grid 96 x 256 = 24576.
// Coalesced reads; scattered stores (no dependent consumer -> absorbed).
// ---------------------------------------------------------------------------
__global__ __launch_bounds__(256) void wtrans_kernel(
        const float* __restrict__ wt,
        const float* __restrict__ wp,
        const float* __restrict__ wg) {
    int i = blockIdx.x * 256 + threadIdx.x;
    if (i < NH * CC) {                    // phi: 8192
        int r = i >> 7, c = i & 127;
        g_wcT[c * CC + r] = wp[i];
    } else if (i < 2 * NH * CC) {         // g: 8192
        int j = i - NH * CC;
        int r = j >> 7, c = j & 127;
        g_wcT[c * CC + NH + r] = wg[j];
    } else {                              // theta: 8192
        int j = i - 2 * NH * CC;
        int r = j >> 7, c = j & 127;
        g_wqT[c * NH + r] = wt[j];
    }
}

// ---------------------------------------------------------------------------
// Merged projections. Weights read straight from transposed globals
// (coalesced LDG, L1-resident). Only the x tile lives in smem (16 KB).
// blocks [0, 576): ctx (phi rows 0-63, g rows 64-127). blocks [576, 720): theta.
// ---------------------------------------------------------------------------
#define TPX 32
#define NPB (HWP / TPX)          // 72

__global__ __launch_bounds__(128) void proj_kernel(const float* __restrict__ x) {
    __shared__ __align__(16) float xs[CC][TPX];   // 16 KB
    int blk = blockIdx.x;
    int tid = threadIdx.x;

    if (blk < BB * TC * NPB) {
        // ----- context frames -----
        int pb = blk % NPB;
        int t  = (blk / NPB) % TC;
        int b  = blk / (NPB * TC);
        int pix0 = pb * TPX;

        const float* xb = x + ((long)(b * CC) * TT + (t + 1)) * HWP + pix0;
        for (int i = tid; i < CC * TPX; i += 128) {
            int c = i >> 5, px = i & 31;
            xs[c][px] = xb[(long)c * TT * HWP + px];   // 128B coalesced
        }
        __syncthreads();

        int r = tid;                       // output row 0..127
        u64t acc2[16];
#pragma unroll
        for (int v = 0; v < 16; v++) acc2[v] = 0ull;

#pragma unroll 4
        for (int c = 0; c < CC; c++) {
            float w = g_wcT[c * CC + r];            // coalesced, L1-hot
            u64t w2 = pk2(w, w);
            const ulonglong2* xr = (const ulonglong2*)&xs[c][0];
#pragma unroll
            for (int v = 0; v < 8; v++) {           // broadcast LDS.128
                ulonglong2 p = xr[v];
                FMA2(acc2[2*v],     w2, p.x, acc2[2*v]);
                FMA2(acc2[2*v + 1], w2, p.y, acc2[2*v + 1]);
            }
        }

        float af[TPX];
#pragma unroll
        for (int v = 0; v < 16; v++) upk2(acc2[v], af[2*v], af[2*v+1]);

        float* ob = ((r < NH) ? g_phiT : g_gvT)
                  + ((long)(b * NH + (r & (NH - 1))) * TC + t) * HWP + pix0;
#pragma unroll
        for (int pp = 0; pp < TPX; pp += 4)
            *(float4*)(ob + pp) = make_float4(af[pp], af[pp+1], af[pp+2], af[pp+3]);
    } else {
        // ----- query frame: theta -> g_q -----
        int blk2 = blk - BB * TC * NPB;
        int pb = blk2 % NPB;
        int b  = blk2 / NPB;
        int pix0 = pb * TPX;

        const float* xb = x + ((long)(b * CC) * TT) * HWP + pix0;
        for (int i = tid; i < CC * TPX; i += 128) {
            int c = i >> 5, px = i & 31;
            xs[c][px] = xb[(long)c * TT * HWP + px];
        }
        __syncthreads();

        int r  = tid & 63;
        int hf = tid >> 6;                 // 16-px half
        u64t acc2[8];
#pragma unroll
        for (int v = 0; v < 8; v++) acc2[v] = 0ull;

#pragma unroll 4
        for (int c = 0; c < CC; c++) {
            float w = g_wqT[c * NH + r];
            u64t w2 = pk2(w, w);
            const ulonglong2* xr = (const ulonglong2*)&xs[c][hf * 16];
#pragma unroll
            for (int v = 0; v < 4; v++) {
                ulonglong2 p = xr[v];
                FMA2(acc2[2*v],     w2, p.x, acc2[2*v]);
                FMA2(acc2[2*v + 1], w2, p.y, acc2[2*v + 1]);
            }
        }

        float af[16];
#pragma unroll
        for (int v = 0; v < 8; v++) upk2(acc2[v], af[2*v], af[2*v+1]);

        long base = (long)b * HWP + pix0 + hf * 16;
#pragma unroll
        for (int pp = 0; pp < 16; pp++) g_q[(base + pp) * NH + r] = af[pp];
    }
}

// ---------------------------------------------------------------------------
// Attention per query pixel (measured-fast structure, unchanged):
// thread-per-key QK, softmax, branchless scrambled AV. block = 256.
//   AV scramble: G[k,h'] = g(head=(64k+h')/196, key=(64k+h')%196)
// Writes Y in the scrambled layout: Z[b][(p%36)*64+h'][p/36].
// ---------------------------------------------------------------------------
__global__ __launch_bounds__(256) void attn_kernel() {
    int bp  = blockIdx.x;               // 0 .. B*HWP-1
    int b   = bp / HWP;
    int pix = bp % HWP;
    int y0  = pix / WW;
    int x0  = pix % WW;
    int tid  = threadIdx.x;
    int warp = tid >> 5;
    int lane = tid & 31;

    __shared__ float qs[NH];
    __shared__ float att[NK];
    __shared__ int   ntp[NK];          // tf*HWP + neighbor pixel
    __shared__ float ypart[4][NH];
    __shared__ float red[16];

    if (tid < NH) qs[tid] = g_q[((long)b * HWP + pix) * NH + tid];

    if (tid < NK) {
        int k   = tid;
        int tf  = k / 49;
        int off = k % 49;
        int dy  = off / 7 - PAD;
        int dx  = off % 7 - PAD;
        int ny  = min(max(y0 + dy, 0), HH - 1);
        int nx  = min(max(x0 + dx, 0), WW - 1);
        ntp[k] = tf * HWP + ny * WW + nx;
    }
    __syncthreads();

    // ---- QK: one thread per key; 64 independent L2 loads ----
    if (tid < NK) {
        const float* pb0 = g_phiT + (long)b * NH * FRAME + ntp[tid];
        float d = 0.f;
#pragma unroll 8
        for (int h = 0; h < NH; h++)
            d += qs[h] * pb0[h * FRAME];
        att[tid] = d * 8.0f;            // * sqrt(64)
    }
    __syncthreads();

    // ---- softmax over 196 ----
    float v = (tid < NK) ? att[tid] : -1e30f;
    float m = v;
#pragma unroll
    for (int s = 16; s > 0; s >>= 1) m = fmaxf(m, __shfl_xor_sync(0xffffffffu, m, s));
    if (lane == 0) red[warp] = m;
    __syncthreads();
    if (tid == 0) {
        float mm = red[0];
#pragma unroll
        for (int w = 1; w < 8; w++) mm = fmaxf(mm, red[w]);
        red[8] = mm;
    }
    __syncthreads();
    m = red[8];

    float e = (tid < NK) ? __expf(v - m) : 0.f;
    float ssum = e;
#pragma unroll
    for (int s = 16; s > 0; s >>= 1) ssum += __shfl_xor_sync(0xffffffffu, ssum, s);
    if (lane == 0) red[warp] = ssum;
    __syncthreads();
    if (tid == 0) {
        float t2 = red[0];
#pragma unroll
        for (int w = 1; w < 8; w++) t2 += red[w];
        red[9] = 1.f / t2;
    }
    __syncthreads();
    if (tid < NK) att[tid] = e * red[9];
    __syncthreads();

    // ---- AV (scrambled), branchless const-div, 4-way k-split ----
    {
        int q = tid >> 6;                 // 0..3
        int h = tid & (NH - 1);
        int kbeg = q * 49;
        const float* gbase = g_gvT + (long)b * NH * FRAME;

        float acc = 0.f;
#pragma unroll 7
        for (int k = kbeg; k < kbeg + 49; k++) {
            int flat = k * NH + h;
            int hh = flat / NK;           // constant divisor -> mul/shift
            int kk = flat - hh * NK;
            acc += att[k] * gbase[hh * FRAME + ntp[kk]];
        }
        ypart[q][h] = acc;
    }
    __syncthreads();
    if (tid < NH) {
        float yv = ypart[0][tid] + ypart[1][tid] + ypart[2][tid] + ypart[3][tid];
        // Y[b,p,h'] -> Z[b, (p%36)*64+h', p/36]
        int p2 = (pix % 36) * 64 + tid;
        int h2 = pix / 36;
        g_z[((long)b * HWP + p2) * NH + h2] = yv;
    }
}

// ---------------------------------------------------------------------------
// Out projection + residual (f32x2):
//   out[b,c,p2] = x[b,c,0,p2] + sum_h2 w_out[c,h2] * Z[b,p2,h2]
// block = 128 (c = tid), 32 pixels per block; coalesced Z loads.
// ---------------------------------------------------------------------------
#define OPX 32
#define ZPITCH 36
__global__ __launch_bounds__(128) void outproj_kernel(
        const float* __restrict__ x,
        const float* __restrict__ w_out,
        float* __restrict__ out) {
    int blk = blockIdx.x;
    int b   = blk / (HWP / OPX);
    int p20 = (blk % (HWP / OPX)) * OPX;
    int tid = threadIdx.x;

    __shared__ __align__(16) float zs[NH][ZPITCH];   // [h2][px]
    for (int i = tid; i < OPX * NH; i += 128) {
        int h2 = i & (NH - 1);                       // coalesced g_z read
        int px = i >> 6;
        zs[h2][px] = g_z[((long)b * HWP + p20 + px) * NH + h2];
    }
    __syncthreads();

    int c = tid;
    const float* wr = w_out + c * NH;

    u64t acc2[16];
#pragma unroll
    for (int v = 0; v < 16; v++) acc2[v] = 0ull;

    for (int h2 = 0; h2 < NH; h2++) {
        float w = wr[h2];
        u64t w2 = pk2(w, w);
        const ulonglong2* zr = (const ulonglong2*)&zs[h2][0];
#pragma unroll
        for (int v = 0; v < 8; v++) {
            ulonglong2 p = zr[v];
            FMA2(acc2[2*v],     w2, p.x, acc2[2*v]);
            FMA2(acc2[2*v + 1], w2, p.y, acc2[2*v + 1]);
        }
    }

    float af[OPX];
#pragma unroll
    for (int v = 0; v < 16; v++) upk2(acc2[v], af[2*v], af[2*v+1]);

    const float* xr   = x   + (((long)(b * CC + c)) * TT + 0) * HWP + p20;
    float*       orow = out + ((long)(b * CC + c)) * HWP + p20;
#pragma unroll
    for (int j = 0; j < OPX; j += 4) {
        float4 xv = *(const float4*)(xr + j);
        *(float4*)(orow + j) = make_float4(xv.x + af[j],     xv.y + af[j + 1],
                                           xv.z + af[j + 2], xv.w + af[j + 3]);
    }
}

extern "C" void kernel_launch(void* const* d_in, const int* in_sizes, int n_in,
                              void* d_out, int out_size) {
    const float* x       = (const float*)d_in[0];
    const float* w_theta = (const float*)d_in[1];
    const float* w_phi   = (const float*)d_in[2];
    const float* w_g     = (const float*)d_in[3];
    const float* w_out   = (const float*)d_in[4];
    float* out = (float*)d_out;

    wtrans_kernel<<<96, 256>>>(w_theta, w_phi, w_g);
    proj_kernel<<<BB * TC * NPB + BB * NPB, 128>>>(x);
    attn_kernel<<<BB * HWP, 256>>>();
    outproj_kernel<<<BB * (HWP / OPX), 128>>>(x, w_out, out);
}

// round 15
// speedup vs baseline: 2.0253x; 1.0533x over previous
#include <cuda_runtime.h>

#define BB 2
#define CC 128
#define TT 5
#define HH 48
#define WW 48
#define HWP 2304      // H*W
#define NH 64         // heads
#define TC 4          // context frames
#define PAD 3
#define NK 196        // Tc*7*7
#define FRAME (TC * HWP)

// Scratch (allocation-free rule: __device__ globals)
__device__ float g_q   [BB * HWP * NH];      // [b][pix][h]
__device__ float g_phi2[BB * TC * HWP * NH]; // [b][t][pix][h]  (QK: key-contiguous)
__device__ float g_gvT [BB * NH * FRAME];    // [b][h][t][pix]  (AV: lane-contiguous)
__device__ float g_z   [BB * HWP * NH];      // [b][p2][h2]     (scrambled Y)
__device__ float g_wcT [CC * CC];            // [c][r]: r<64 phi row, r>=64 g row
__device__ float g_wqT [CC * NH];            // [c][r]: theta rows
__device__ float g_woT [NH * CC];            // [h2][c]: w_out transposed

typedef unsigned long long u64t;
__device__ __forceinline__ u64t pk2(float lo, float hi) {
    u64t r; asm("mov.b64 %0,{%1,%2};" : "=l"(r) : "f"(lo), "f"(hi)); return r;
}
__device__ __forceinline__ void upk2(u64t v, float& lo, float& hi) {
    asm("mov.b64 {%0,%1},%2;" : "=f"(lo), "=f"(hi) : "l"(v));
}
#define FMA2(d, a, b, c) asm("fma.rn.f32x2 %0,%1,%2,%3;" : "=l"(d) : "l"(a), "l"(b), "l"(c))

// ---------------------------------------------------------------------------
// One-time weight transposes (coalesced reads, scattered stores absorbed).
// 4 matrices x 8192 elements = 32768 threads -> grid 128 x 256.
// ---------------------------------------------------------------------------
__global__ __launch_bounds__(256) void wtrans_kernel(
        const float* __restrict__ wt,
        const float* __restrict__ wp,
        const float* __restrict__ wg,
        const float* __restrict__ wo) {
    int i = blockIdx.x * 256 + threadIdx.x;
    if (i < NH * CC) {                    // phi
        int r = i >> 7, c = i & 127;
        g_wcT[c * CC + r] = wp[i];
    } else if (i < 2 * NH * CC) {         // g
        int j = i - NH * CC;
        int r = j >> 7, c = j & 127;
        g_wcT[c * CC + NH + r] = wg[j];
    } else if (i < 3 * NH * CC) {         // theta
        int j = i - 2 * NH * CC;
        int r = j >> 7, c = j & 127;
        g_wqT[c * NH + r] = wt[j];
    } else {                              // w_out [CC][NH] -> [NH][CC]
        int j = i - 3 * NH * CC;
        int c = j >> 6, h2 = j & 63;
        g_woT[h2 * CC + c] = wo[j];
    }
}

// ---------------------------------------------------------------------------
// Merged projections. Weights from transposed globals (coalesced, L1-hot).
// blocks [0, 576): ctx (phi rows 0-63 -> g_phi2, g rows 64-127 -> g_gvT).
// blocks [576, 720): theta -> g_q.
// ---------------------------------------------------------------------------
#define TPX 32
#define NPB (HWP / TPX)          // 72

__global__ __launch_bounds__(128) void proj_kernel(const float* __restrict__ x) {
    __shared__ __align__(16) float xs[CC][TPX];   // 16 KB
    int blk = blockIdx.x;
    int tid = threadIdx.x;

    if (blk < BB * TC * NPB) {
        // ----- context frames -----
        int pb = blk % NPB;
        int t  = (blk / NPB) % TC;
        int b  = blk / (NPB * TC);
        int pix0 = pb * TPX;

        const float* xb = x + ((long)(b * CC) * TT + (t + 1)) * HWP + pix0;
        for (int i = tid; i < CC * TPX; i += 128) {
            int c = i >> 5, px = i & 31;
            xs[c][px] = xb[(long)c * TT * HWP + px];
        }
        __syncthreads();

        int r = tid;                       // output row 0..127
        u64t acc2[16];
#pragma unroll
        for (int v = 0; v < 16; v++) acc2[v] = 0ull;

#pragma unroll 4
        for (int c = 0; c < CC; c++) {
            float w = g_wcT[c * CC + r];            // coalesced, L1-hot
            u64t w2 = pk2(w, w);
            const ulonglong2* xr = (const ulonglong2*)&xs[c][0];
#pragma unroll
            for (int v = 0; v < 8; v++) {
                ulonglong2 p = xr[v];
                FMA2(acc2[2*v],     w2, p.x, acc2[2*v]);
                FMA2(acc2[2*v + 1], w2, p.y, acc2[2*v + 1]);
            }
        }

        float af[TPX];
#pragma unroll
        for (int v = 0; v < 16; v++) upk2(acc2[v], af[2*v], af[2*v+1]);

        if (r < NH) {
            // phi -> [b][t][pix][h]: lanes r adjacent -> coalesced 128B stores
            float* ob = g_phi2 + ((long)(b * TC + t) * HWP + pix0) * NH + r;
#pragma unroll
            for (int pp = 0; pp < TPX; pp++) ob[pp * NH] = af[pp];
        } else {
            float* ob = g_gvT
                      + ((long)(b * NH + (r - NH)) * TC + t) * HWP + pix0;
#pragma unroll
            for (int pp = 0; pp < TPX; pp += 4)
                *(float4*)(ob + pp) = make_float4(af[pp], af[pp+1], af[pp+2], af[pp+3]);
        }
    } else {
        // ----- query frame: theta -> g_q -----
        int blk2 = blk - BB * TC * NPB;
        int pb = blk2 % NPB;
        int b  = blk2 / NPB;
        int pix0 = pb * TPX;

        const float* xb = x + ((long)(b * CC) * TT) * HWP + pix0;
        for (int i = tid; i < CC * TPX; i += 128) {
            int c = i >> 5, px = i & 31;
            xs[c][px] = xb[(long)c * TT * HWP + px];
        }
        __syncthreads();

        int r  = tid & 63;
        int hf = tid >> 6;                 // 16-px half
        u64t acc2[8];
#pragma unroll
        for (int v = 0; v < 8; v++) acc2[v] = 0ull;

#pragma unroll 4
        for (int c = 0; c < CC; c++) {
            float w = g_wqT[c * NH + r];
            u64t w2 = pk2(w, w);
            const ulonglong2* xr = (const ulonglong2*)&xs[c][hf * 16];
#pragma unroll
            for (int v = 0; v < 4; v++) {
                ulonglong2 p = xr[v];
                FMA2(acc2[2*v],     w2, p.x, acc2[2*v]);
                FMA2(acc2[2*v + 1], w2, p.y, acc2[2*v + 1]);
            }
        }

        float af[16];
#pragma unroll
        for (int v = 0; v < 8; v++) upk2(acc2[v], af[2*v], af[2*v+1]);

        long base = (long)b * HWP + pix0 + hf * 16;
#pragma unroll
        for (int pp = 0; pp < 16; pp++) g_q[(base + pp) * NH + r] = af[pp];
    }
}

// ---------------------------------------------------------------------------
// Attention per query pixel. Warp-per-key QK on [t][pix][h] phi (contiguous
// 256B per key), softmax, branchless scrambled AV on [h][t][pix] g.
// block = 256. Writes scrambled Z[b][(p%36)*64+h'][p/36].
// ---------------------------------------------------------------------------
__global__ __launch_bounds__(256) void attn_kernel() {
    int bp  = blockIdx.x;               // 0 .. B*HWP-1
    int b   = bp / HWP;
    int pix = bp % HWP;
    int y0  = pix / WW;
    int x0  = pix % WW;
    int tid  = threadIdx.x;
    int warp = tid >> 5;
    int lane = tid & 31;

    __shared__ __align__(16) float qs[NH];
    __shared__ float att[NK];
    __shared__ int   ntp[NK];          // tf*HWP + neighbor pixel
    __shared__ float ypart[4][NH];
    __shared__ float red[16];

    if (tid < NH) qs[tid] = g_q[((long)b * HWP + pix) * NH + tid];

    if (tid < NK) {
        int k   = tid;
        int tf  = k / 49;
        int off = k % 49;
        int dy  = off / 7 - PAD;
        int dx  = off % 7 - PAD;
        int ny  = min(max(y0 + dy, 0), HH - 1);
        int nx  = min(max(x0 + dx, 0), WW - 1);
        ntp[k] = tf * HWP + ny * WW + nx;
    }
    __syncthreads();

    // ---- QK: warp per key; coalesced float2 loads (256 B/key), shfl tree ----
    {
        float2 qv = ((const float2*)qs)[lane];
        const float* phib = g_phi2 + (long)b * TC * HWP * NH;
        for (int k = warp; k < NK; k += 8) {
            const float2* pr = (const float2*)(phib + ntp[k] * NH);
            float2 a = pr[lane];
            float d = qv.x * a.x + qv.y * a.y;
#pragma unroll
            for (int s = 16; s > 0; s >>= 1)
                d += __shfl_xor_sync(0xffffffffu, d, s);
            if (lane == 0) att[k] = d * 8.0f;      // * sqrt(64)
        }
    }
    __syncthreads();

    // ---- softmax over 196 ----
    float v = (tid < NK) ? att[tid] : -1e30f;
    float m = v;
#pragma unroll
    for (int s = 16; s > 0; s >>= 1) m = fmaxf(m, __shfl_xor_sync(0xffffffffu, m, s));
    if (lane == 0) red[warp] = m;
    __syncthreads();
    if (tid == 0) {
        float mm = red[0];
#pragma unroll
        for (int w = 1; w < 8; w++) mm = fmaxf(mm, red[w]);
        red[8] = mm;
    }
    __syncthreads();
    m = red[8];

    float e = (tid < NK) ? __expf(v - m) : 0.f;
    float ssum = e;
#pragma unroll
    for (int s = 16; s > 0; s >>= 1) ssum += __shfl_xor_sync(0xffffffffu, ssum, s);
    if (lane == 0) red[warp] = ssum;
    __syncthreads();
    if (tid == 0) {
        float t2 = red[0];
#pragma unroll
        for (int w = 1; w < 8; w++) t2 += red[w];
        red[9] = 1.f / t2;
    }
    __syncthreads();
    if (tid < NK) att[tid] = e * red[9];
    __syncthreads();

    // ---- AV (scrambled): G[k,h']=g(head=(64k+h')/196, key=(64k+h')%196) ----
    {
        int q = tid >> 6;                 // 0..3
        int h = tid & (NH - 1);
        int kbeg = q * 49;
        const float* gbase = g_gvT + (long)b * NH * FRAME;

        float acc = 0.f;
#pragma unroll 7
        for (int k = kbeg; k < kbeg + 49; k++) {
            int flat = k * NH + h;
            int hh = flat / NK;           // constant divisor -> mul/shift
            int kk = flat - hh * NK;
            acc += att[k] * gbase[hh * FRAME + ntp[kk]];
        }
        ypart[q][h] = acc;
    }
    __syncthreads();
    if (tid < NH) {
        float yv = ypart[0][tid] + ypart[1][tid] + ypart[2][tid] + ypart[3][tid];
        // Y[b,p,h'] -> Z[b, (p%36)*64+h', p/36]
        int p2 = (pix % 36) * 64 + tid;
        int h2 = pix / 36;
        g_z[((long)b * HWP + p2) * NH + h2] = yv;
    }
}

// ---------------------------------------------------------------------------
// Out projection + residual (f32x2, transposed weights, split-h2):
//   out[b,c,p2] = x[b,c,0,p2] + sum_h2 w_out[c,h2] * Z[b,p2,h2]
// block = 256: c = tid&127, kh = tid>>7 (h2 half). 16 pixels per block.
// ---------------------------------------------------------------------------
#define OPX 16
__global__ __launch_bounds__(256) void outproj_kernel(
        const float* __restrict__ x,
        float* __restrict__ out) {
    int blk = blockIdx.x;
    int b   = blk / (HWP / OPX);
    int p20 = (blk % (HWP / OPX)) * OPX;
    int tid = threadIdx.x;
    int c   = tid & 127;
    int kh  = tid >> 7;

    __shared__ __align__(16) float zs[NH][OPX];      // 4 KB  [h2][px]
    __shared__ __align__(16) float part[CC][OPX];    // 8 KB

    for (int i = tid; i < NH * OPX; i += 256) {
        int h2 = i & (NH - 1);                       // coalesced g_z read
        int px = i >> 6;
        zs[h2][px] = g_z[((long)b * HWP + p20 + px) * NH + h2];
    }
    __syncthreads();

    u64t acc2[OPX / 2];
#pragma unroll
    for (int v = 0; v < OPX / 2; v++) acc2[v] = 0ull;

    int h0 = kh * 32;
#pragma unroll 4
    for (int h2 = h0; h2 < h0 + 32; h2++) {
        float w = g_woT[h2 * CC + c];                // lane-consecutive, L1-hot
        u64t w2 = pk2(w, w);
        const ulonglong2* zr = (const ulonglong2*)&zs[h2][0];
#pragma unroll
        for (int v = 0; v < OPX / 4; v++) {
            ulonglong2 p = zr[v];
            FMA2(acc2[2*v],     w2, p.x, acc2[2*v]);
            FMA2(acc2[2*v + 1], w2, p.y, acc2[2*v + 1]);
        }
    }

    float af[OPX];
#pragma unroll
    for (int v = 0; v < OPX / 2; v++) upk2(acc2[v], af[2*v], af[2*v+1]);

    if (kh == 1) {
#pragma unroll
        for (int j = 0; j < OPX; j++) part[c][j] = af[j];
    }
    __syncthreads();
    if (kh == 0) {
        const float* xr   = x   + (((long)(b * CC + c)) * TT + 0) * HWP + p20;
        float*       orow = out + ((long)(b * CC + c)) * HWP + p20;
#pragma unroll
        for (int j = 0; j < OPX; j += 4) {
            float4 xv = *(const float4*)(xr + j);
            *(float4*)(orow + j) = make_float4(
                xv.x + af[j]     + part[c][j],
                xv.y + af[j + 1] + part[c][j + 1],
                xv.z + af[j + 2] + part[c][j + 2],
                xv.w + af[j + 3] + part[c][j + 3]);
        }
    }
}

extern "C" void kernel_launch(void* const* d_in, const int* in_sizes, int n_in,
                              void* d_out, int out_size) {
    const float* x       = (const float*)d_in[0];
    const float* w_theta = (const float*)d_in[1];
    const float* w_phi   = (const float*)d_in[2];
    const float* w_g     = (const float*)d_in[3];
    const float* w_out   = (const float*)d_in[4];
    float* out = (float*)d_out;

    wtrans_kernel<<<128, 256>>>(w_theta, w_phi, w_g, w_out);
    proj_kernel<<<BB * TC * NPB + BB * NPB, 128>>>(x);
    attn_kernel<<<BB * HWP, 256>>>();
    outproj_kernel<<<BB * (HWP / OPX), 256>>>(x, out);
}